// round 14
// baseline (speedup 1.0000x reference)
#include <cuda_runtime.h>
#include <cuda_bf16.h>

// KL(p||q) for diagonal Gaussians, mean over batch. SINGLE kernel.
// Main loop: plain grid-stride float4 (1024x256) — the only form ptxas
// schedules at ~6 TB/s (5 hand-tuned variants all lost).
// Tail: packed fixed-point (x2^20) u64 atomicAdd SPREAD over 32 slots
// (blockIdx & 31) -> ~32-way less L2 atomic serialization than one slot.
// Ticket counter picks the last block, which sums the 32 slots in fixed
// order (integer adds commute -> deterministic), writes out[0], and resets
// slots + ticket for graph replay.

#define NBLOCKS 1024
#define NTHREADS 256
#define NSLOTS 32
#define FIXED_SCALE 1048576.0   // 2^20

__device__ unsigned long long g_slots[NSLOTS];   // zero-initialized
__device__ unsigned int g_ticket = 0;

__global__ __launch_bounds__(NTHREADS) void kl_onepass_kernel(
    const float* __restrict__ p_mu,
    const float* __restrict__ p_lv,
    const float* __restrict__ q_mu,
    const float* __restrict__ q_lv,
    float* __restrict__ out,
    int n4, float scale)
{
    const float4* pm4 = reinterpret_cast<const float4*>(p_mu);
    const float4* pl4 = reinterpret_cast<const float4*>(p_lv);
    const float4* qm4 = reinterpret_cast<const float4*>(q_mu);
    const float4* ql4 = reinterpret_cast<const float4*>(q_lv);

    float acc = 0.0f;
    int stride = gridDim.x * blockDim.x;
    for (int i = blockIdx.x * blockDim.x + threadIdx.x; i < n4; i += stride) {
        float4 a = pm4[i];
        float4 b = pl4[i];
        float4 c = qm4[i];
        float4 d = ql4[i];

        {
            float lr = d.x - b.x;
            float dm = a.x - c.x;
            acc += lr + __expf(-lr) + dm * dm * __expf(-d.x) - 1.0f;
        }
        {
            float lr = d.y - b.y;
            float dm = a.y - c.y;
            acc += lr + __expf(-lr) + dm * dm * __expf(-d.y) - 1.0f;
        }
        {
            float lr = d.z - b.z;
            float dm = a.z - c.z;
            acc += lr + __expf(-lr) + dm * dm * __expf(-d.z) - 1.0f;
        }
        {
            float lr = d.w - b.w;
            float dm = a.w - c.w;
            acc += lr + __expf(-lr) + dm * dm * __expf(-d.w) - 1.0f;
        }
    }

    // Block reduce
    #pragma unroll
    for (int off = 16; off > 0; off >>= 1)
        acc += __shfl_down_sync(0xFFFFFFFFu, acc, off);

    __shared__ float smem[NTHREADS / 32];
    __shared__ bool s_is_last;
    int lane = threadIdx.x & 31;
    int warp = threadIdx.x >> 5;
    if (lane == 0) smem[warp] = acc;
    __syncthreads();

    if (warp == 0) {
        acc = (lane < NTHREADS / 32) ? smem[lane] : 0.0f;
        #pragma unroll
        for (int off = 4; off > 0; off >>= 1)
            acc += __shfl_down_sync(0xFFFFFFFFu, acc, off);

        if (lane == 0) {
            // Non-negative KL partial -> fixed point; spread across 32 slots.
            unsigned long long mine =
                (unsigned long long)__double2ll_rn((double)acc * FIXED_SCALE);
            atomicAdd(&g_slots[blockIdx.x & (NSLOTS - 1)], mine);
            __threadfence();
            unsigned int t = atomicAdd(&g_ticket, 1u);
            s_is_last = (t == (unsigned int)(NBLOCKS - 1));
        }
    }
    __syncthreads();

    if (!s_is_last) return;

    // Last block, warp 0: sum the 32 slots in fixed order (deterministic —
    // integer adds commute, so arrival order is irrelevant), then reset.
    if (warp == 0) {
        volatile unsigned long long* vs = (volatile unsigned long long*)g_slots;
        unsigned long long v = (lane < NSLOTS) ? vs[lane] : 0ULL;

        #pragma unroll
        for (int off = 16; off > 0; off >>= 1)
            v += __shfl_down_sync(0xFFFFFFFFu, v, off);

        if (lane == 0) {
            out[0] = (float)((double)v * (1.0 / FIXED_SCALE) * (double)scale);
        }
        if (lane < NSLOTS) vs[lane] = 0ULL;   // reset slots for next replay
        if (lane == 0) {
            g_ticket = 0;                      // reset ticket
            __threadfence();
        }
    }
}

extern "C" void kernel_launch(void* const* d_in, const int* in_sizes, int n_in,
                              void* d_out, int out_size)
{
    const float* p_mu = (const float*)d_in[0];
    const float* p_lv = (const float*)d_in[1];
    const float* q_mu = (const float*)d_in[2];
    const float* q_lv = (const float*)d_in[3];
    float* out = (float*)d_out;

    int n  = in_sizes[0];     // B*D
    int n4 = n >> 2;
    int B  = n / 512;         // D = 512
    float scale = 0.5f / (float)B;

    kl_onepass_kernel<<<NBLOCKS, NTHREADS>>>(p_mu, p_lv, q_mu, q_lv, out, n4, scale);
}

// round 15
// speedup vs baseline: 1.0036x; 1.0036x over previous
#include <cuda_runtime.h>
#include <cuda_bf16.h>

// KL(p||q) for diagonal Gaussians, mean over batch. SINGLE kernel.
// Main loop: plain grid-stride float4 — only form ptxas schedules at ~6TB/s.
// Change vs R14: 2048 blocks (4 exact iters/thread) -> halves the per-CTA
// work quantum, shrinking end-of-kernel straggler skew.
// Tail: packed fixed-point (x2^20) u64 atomicAdd spread over 64 slots;
// ticket picks last block, which sums slots in fixed order (integer adds
// commute -> deterministic), writes out[0], resets state for graph replay.

#define NBLOCKS 2048
#define NTHREADS 256
#define NSLOTS 64
#define FIXED_SCALE 1048576.0   // 2^20

__device__ unsigned long long g_slots[NSLOTS];   // zero-initialized
__device__ unsigned int g_ticket = 0;

__global__ __launch_bounds__(NTHREADS) void kl_onepass_kernel(
    const float* __restrict__ p_mu,
    const float* __restrict__ p_lv,
    const float* __restrict__ q_mu,
    const float* __restrict__ q_lv,
    float* __restrict__ out,
    int n4, float scale)
{
    const float4* pm4 = reinterpret_cast<const float4*>(p_mu);
    const float4* pl4 = reinterpret_cast<const float4*>(p_lv);
    const float4* qm4 = reinterpret_cast<const float4*>(q_mu);
    const float4* ql4 = reinterpret_cast<const float4*>(q_lv);

    float acc = 0.0f;
    int stride = gridDim.x * blockDim.x;
    for (int i = blockIdx.x * blockDim.x + threadIdx.x; i < n4; i += stride) {
        float4 a = pm4[i];
        float4 b = pl4[i];
        float4 c = qm4[i];
        float4 d = ql4[i];

        {
            float lr = d.x - b.x;
            float dm = a.x - c.x;
            acc += lr + __expf(-lr) + dm * dm * __expf(-d.x) - 1.0f;
        }
        {
            float lr = d.y - b.y;
            float dm = a.y - c.y;
            acc += lr + __expf(-lr) + dm * dm * __expf(-d.y) - 1.0f;
        }
        {
            float lr = d.z - b.z;
            float dm = a.z - c.z;
            acc += lr + __expf(-lr) + dm * dm * __expf(-d.z) - 1.0f;
        }
        {
            float lr = d.w - b.w;
            float dm = a.w - c.w;
            acc += lr + __expf(-lr) + dm * dm * __expf(-d.w) - 1.0f;
        }
    }

    // Block reduce
    #pragma unroll
    for (int off = 16; off > 0; off >>= 1)
        acc += __shfl_down_sync(0xFFFFFFFFu, acc, off);

    __shared__ float smem[NTHREADS / 32];
    __shared__ bool s_is_last;
    int lane = threadIdx.x & 31;
    int warp = threadIdx.x >> 5;
    if (lane == 0) smem[warp] = acc;
    __syncthreads();

    if (warp == 0) {
        acc = (lane < NTHREADS / 32) ? smem[lane] : 0.0f;
        #pragma unroll
        for (int off = 4; off > 0; off >>= 1)
            acc += __shfl_down_sync(0xFFFFFFFFu, acc, off);

        if (lane == 0) {
            // Non-negative KL partial -> fixed point; spread across 64 slots.
            unsigned long long mine =
                (unsigned long long)__double2ll_rn((double)acc * FIXED_SCALE);
            atomicAdd(&g_slots[blockIdx.x & (NSLOTS - 1)], mine);
            __threadfence();
            unsigned int t = atomicAdd(&g_ticket, 1u);
            s_is_last = (t == (unsigned int)(NBLOCKS - 1));
        }
    }
    __syncthreads();

    if (!s_is_last) return;

    // Last block, warps 0-1 hold the 64 slots; do it with warp 0 over 2 loads
    // in fixed order (integer adds commute -> order-independent anyway).
    if (warp == 0) {
        volatile unsigned long long* vs = (volatile unsigned long long*)g_slots;
        unsigned long long v = vs[lane] + vs[lane + 32];

        #pragma unroll
        for (int off = 16; off > 0; off >>= 1)
            v += __shfl_down_sync(0xFFFFFFFFu, v, off);

        if (lane == 0) {
            out[0] = (float)((double)v * (1.0 / FIXED_SCALE) * (double)scale);
        }
        vs[lane] = 0ULL;            // reset slots for next replay
        vs[lane + 32] = 0ULL;
        if (lane == 0) {
            g_ticket = 0;           // reset ticket
            __threadfence();
        }
    }
}

extern "C" void kernel_launch(void* const* d_in, const int* in_sizes, int n_in,
                              void* d_out, int out_size)
{
    const float* p_mu = (const float*)d_in[0];
    const float* p_lv = (const float*)d_in[1];
    const float* q_mu = (const float*)d_in[2];
    const float* q_lv = (const float*)d_in[3];
    float* out = (float*)d_out;

    int n  = in_sizes[0];     // B*D
    int n4 = n >> 2;
    int B  = n / 512;         // D = 512
    float scale = 0.5f / (float)B;

    kl_onepass_kernel<<<NBLOCKS, NTHREADS>>>(p_mu, p_lv, q_mu, q_lv, out, n4, scale);
}

// round 16
// speedup vs baseline: 1.0132x; 1.0096x over previous
#include <cuda_runtime.h>
#include <cuda_bf16.h>

// KL(p||q) for diagonal Gaussians, mean over batch.  FINAL (R8 architecture).
//
// 15 rounds of measurement established:
//  - plain grid-stride float4 loop @ 1024x256 is the fastest main loop
//    (~5.9-6.5 TB/s); every hand-tuned variant (manual/pragma/compile-time
//    unroll, .cs hints, bulk-async pipeline, other grids) regressed.
//  - best tail = PDL finish kernel that HW-sleeps in
//    cudaGridDependencySynchronize(): launch latency hidden behind the
//    primary, zero in-primary atomic cost, ~0.4us exposed.
// Deterministic: fixed grid, fixed reduction order, no float atomics.

#define NBLOCKS 1024
#define NTHREADS 256

__device__ float g_partials[NBLOCKS];

__global__ __launch_bounds__(NTHREADS) void kl_partial_kernel(
    const float* __restrict__ p_mu,
    const float* __restrict__ p_lv,
    const float* __restrict__ q_mu,
    const float* __restrict__ q_lv,
    int n4)
{
    // Release the dependent (finish) kernel immediately; it blocks in
    // cudaGridDependencySynchronize() until this grid completes.
    cudaTriggerProgrammaticLaunchCompletion();

    const float4* pm4 = reinterpret_cast<const float4*>(p_mu);
    const float4* pl4 = reinterpret_cast<const float4*>(p_lv);
    const float4* qm4 = reinterpret_cast<const float4*>(q_mu);
    const float4* ql4 = reinterpret_cast<const float4*>(q_lv);

    float acc = 0.0f;
    int stride = gridDim.x * blockDim.x;
    for (int i = blockIdx.x * blockDim.x + threadIdx.x; i < n4; i += stride) {
        float4 a = pm4[i];
        float4 b = pl4[i];
        float4 c = qm4[i];
        float4 d = ql4[i];

        {
            float lr = d.x - b.x;
            float dm = a.x - c.x;
            acc += lr + __expf(-lr) + dm * dm * __expf(-d.x) - 1.0f;
        }
        {
            float lr = d.y - b.y;
            float dm = a.y - c.y;
            acc += lr + __expf(-lr) + dm * dm * __expf(-d.y) - 1.0f;
        }
        {
            float lr = d.z - b.z;
            float dm = a.z - c.z;
            acc += lr + __expf(-lr) + dm * dm * __expf(-d.z) - 1.0f;
        }
        {
            float lr = d.w - b.w;
            float dm = a.w - c.w;
            acc += lr + __expf(-lr) + dm * dm * __expf(-d.w) - 1.0f;
        }
    }

    // warp reduce
    #pragma unroll
    for (int off = 16; off > 0; off >>= 1)
        acc += __shfl_down_sync(0xFFFFFFFFu, acc, off);

    __shared__ float smem[NTHREADS / 32];
    int lane = threadIdx.x & 31;
    int warp = threadIdx.x >> 5;
    if (lane == 0) smem[warp] = acc;
    __syncthreads();

    if (warp == 0) {
        acc = (lane < NTHREADS / 32) ? smem[lane] : 0.0f;
        #pragma unroll
        for (int off = 4; off > 0; off >>= 1)
            acc += __shfl_down_sync(0xFFFFFFFFu, acc, off);
        if (lane == 0) g_partials[blockIdx.x] = acc;
    }
}

__global__ __launch_bounds__(1024) void kl_finish_kernel(float* out, float scale)
{
    // Launched early via PDL; HW-sleep here until the primary grid (and all
    // its memory writes) completes.
    cudaGridDependencySynchronize();

    float acc = g_partials[threadIdx.x];

    #pragma unroll
    for (int off = 16; off > 0; off >>= 1)
        acc += __shfl_down_sync(0xFFFFFFFFu, acc, off);

    __shared__ float smem[32];
    int lane = threadIdx.x & 31;
    int warp = threadIdx.x >> 5;
    if (lane == 0) smem[warp] = acc;
    __syncthreads();

    if (warp == 0) {
        acc = smem[lane];
        #pragma unroll
        for (int off = 16; off > 0; off >>= 1)
            acc += __shfl_down_sync(0xFFFFFFFFu, acc, off);
        if (lane == 0) out[0] = acc * scale;
    }
}

extern "C" void kernel_launch(void* const* d_in, const int* in_sizes, int n_in,
                              void* d_out, int out_size)
{
    const float* p_mu = (const float*)d_in[0];
    const float* p_lv = (const float*)d_in[1];
    const float* q_mu = (const float*)d_in[2];
    const float* q_lv = (const float*)d_in[3];
    float* out = (float*)d_out;

    int n  = in_sizes[0];     // B*D
    int n4 = n >> 2;
    int B  = n / 512;         // D = 512
    float scale = 0.5f / (float)B;

    kl_partial_kernel<<<NBLOCKS, NTHREADS>>>(p_mu, p_lv, q_mu, q_lv, n4);

    // Finish kernel with programmatic dependent launch: overlaps its launch
    // latency with the primary kernel's execution.
    cudaLaunchConfig_t cfg = {};
    cfg.gridDim  = dim3(1, 1, 1);
    cfg.blockDim = dim3(1024, 1, 1);
    cfg.dynamicSmemBytes = 0;
    cfg.stream = 0;
    cudaLaunchAttribute attrs[1];
    attrs[0].id = cudaLaunchAttributeProgrammaticStreamSerialization;
    attrs[0].val.programmaticStreamSerializationAllowed = 1;
    cfg.attrs = attrs;
    cfg.numAttrs = 1;
    cudaLaunchKernelEx(&cfg, kl_finish_kernel, out, scale);
}

// round 17
// speedup vs baseline: 1.0168x; 1.0036x over previous
#include <cuda_runtime.h>
#include <cuda_bf16.h>

// KL(p||q) for diagonal Gaussians, mean over batch. FINAL hybrid:
//  Primary: plain grid-stride float4 loop (1024x256 — measured optimum) +
//           block reduce + ONE spread-slot fixed-point u64 atomicAdd
//           (distinct addresses -> no L2 atomic serialization), then exit.
//           Strictly less tail work than any prior variant.
//  Finish:  PDL-launched, HW-sleeps in cudaGridDependencySynchronize()
//           (launch latency hidden), one warp sums 32 slots in fixed order
//           (integer adds commute -> deterministic), writes out, resets
//           slots for the next graph replay.

#define NBLOCKS 1024
#define NTHREADS 256
#define NSLOTS 32
#define FIXED_SCALE 1048576.0   // 2^20; KL terms are non-negative, sum < 2^50

__device__ unsigned long long g_slots[NSLOTS];   // zero-initialized

__global__ __launch_bounds__(NTHREADS) void kl_partial_kernel(
    const float* __restrict__ p_mu,
    const float* __restrict__ p_lv,
    const float* __restrict__ q_mu,
    const float* __restrict__ q_lv,
    int n4)
{
    // Release the dependent finish kernel; it sleeps until this grid retires.
    cudaTriggerProgrammaticLaunchCompletion();

    const float4* pm4 = reinterpret_cast<const float4*>(p_mu);
    const float4* pl4 = reinterpret_cast<const float4*>(p_lv);
    const float4* qm4 = reinterpret_cast<const float4*>(q_mu);
    const float4* ql4 = reinterpret_cast<const float4*>(q_lv);

    float acc = 0.0f;
    int stride = gridDim.x * blockDim.x;
    for (int i = blockIdx.x * blockDim.x + threadIdx.x; i < n4; i += stride) {
        float4 a = pm4[i];
        float4 b = pl4[i];
        float4 c = qm4[i];
        float4 d = ql4[i];

        {
            float lr = d.x - b.x;
            float dm = a.x - c.x;
            acc += lr + __expf(-lr) + dm * dm * __expf(-d.x) - 1.0f;
        }
        {
            float lr = d.y - b.y;
            float dm = a.y - c.y;
            acc += lr + __expf(-lr) + dm * dm * __expf(-d.y) - 1.0f;
        }
        {
            float lr = d.z - b.z;
            float dm = a.z - c.z;
            acc += lr + __expf(-lr) + dm * dm * __expf(-d.z) - 1.0f;
        }
        {
            float lr = d.w - b.w;
            float dm = a.w - c.w;
            acc += lr + __expf(-lr) + dm * dm * __expf(-d.w) - 1.0f;
        }
    }

    // Block reduce
    #pragma unroll
    for (int off = 16; off > 0; off >>= 1)
        acc += __shfl_down_sync(0xFFFFFFFFu, acc, off);

    __shared__ float smem[NTHREADS / 32];
    int lane = threadIdx.x & 31;
    int warp = threadIdx.x >> 5;
    if (lane == 0) smem[warp] = acc;
    __syncthreads();

    if (warp == 0) {
        acc = (lane < NTHREADS / 32) ? smem[lane] : 0.0f;
        #pragma unroll
        for (int off = 4; off > 0; off >>= 1)
            acc += __shfl_down_sync(0xFFFFFFFFu, acc, off);
        if (lane == 0) {
            // Non-negative partial -> fixed point; one atomic to a spread
            // slot (blockIdx & 31): distinct addresses, no serialization.
            unsigned long long mine =
                (unsigned long long)__double2ll_rn((double)acc * FIXED_SCALE);
            atomicAdd(&g_slots[blockIdx.x & (NSLOTS - 1)], mine);
        }
    }
    // No ticket, no extra sync, no last-block work: block exits immediately.
}

__global__ __launch_bounds__(32) void kl_finish_kernel(float* out, float scale)
{
    // Launched early via PDL; HW-sleep until the primary grid (and all its
    // atomics) completes. PDL guarantees memory visibility.
    cudaGridDependencySynchronize();

    int lane = threadIdx.x;
    unsigned long long v = g_slots[lane];

    #pragma unroll
    for (int off = 16; off > 0; off >>= 1)
        v += __shfl_down_sync(0xFFFFFFFFu, v, off);

    if (lane == 0)
        out[0] = (float)((double)v * (1.0 / FIXED_SCALE) * (double)scale);

    g_slots[lane] = 0ULL;   // reset for next graph replay
}

extern "C" void kernel_launch(void* const* d_in, const int* in_sizes, int n_in,
                              void* d_out, int out_size)
{
    const float* p_mu = (const float*)d_in[0];
    const float* p_lv = (const float*)d_in[1];
    const float* q_mu = (const float*)d_in[2];
    const float* q_lv = (const float*)d_in[3];
    float* out = (float*)d_out;

    int n  = in_sizes[0];     // B*D
    int n4 = n >> 2;
    int B  = n / 512;         // D = 512
    float scale = 0.5f / (float)B;

    kl_partial_kernel<<<NBLOCKS, NTHREADS>>>(p_mu, p_lv, q_mu, q_lv, n4);

    // PDL finish: launch latency overlaps the primary kernel's execution.
    cudaLaunchConfig_t cfg = {};
    cfg.gridDim  = dim3(1, 1, 1);
    cfg.blockDim = dim3(32, 1, 1);
    cfg.dynamicSmemBytes = 0;
    cfg.stream = 0;
    cudaLaunchAttribute attrs[1];
    attrs[0].id = cudaLaunchAttributeProgrammaticStreamSerialization;
    attrs[0].val.programmaticStreamSerializationAllowed = 1;
    cfg.attrs = attrs;
    cfg.numAttrs = 1;
    cudaLaunchKernelEx(&cfg, kl_finish_kernel, out, scale);
}